// round 6
// baseline (speedup 1.0000x reference)
#include <cuda_runtime.h>
#include <cuda_bf16.h>
#include <cstdint>

#define NB    32
#define CC    256
#define HH    56
#define WWD   56
#define HWH   (HH*WWD)        /* 3136  */
#define NPIX  (NB*HWH)        /* 100352 */
#define KKT   2304            /* 256*9 */
#define EPSV  1e-5f

#define M_TILE   128
#define N_TILE   128
#define NCHUNK   18           /* 9 taps x 2 ic-halves, 128B each */
#define STAGE_BYTES 32768     /* A 16KB + B 16KB */
#define DSMEM_BYTES (2*STAGE_BYTES)

// ---------------- static device scratch (no allocations allowed) ----------------
__device__ signed char g_act8[(size_t)NPIX * 256];   // int8 signs of BN output (25.7MB)
__device__ signed char g_w8[(size_t)CC * KKT];       // int8 signs of weights, k=(tap*256+ic)
__device__ float    g_alpha[CC];
__device__ float    g_a[NPIX];                 // channel mean per pixel
__device__ float    g_K[NPIX];                 // 3x3 box of g_a / 9
__device__ float    g_s1[CC], g_h1[CC];
__device__ float    g_s2[CC], g_h2[CC];
__device__ float    g_r[(size_t)NPIX * CC];    // relu(conv1) fp32 (102.8 MB)

// ---------------- PTX helpers ----------------
__device__ __forceinline__ uint32_t smem_u32(const void* p) {
    uint32_t a;
    asm("{ .reg .u64 t; cvta.to.shared.u64 t, %1; cvt.u32.u64 %0, t; }" : "=r"(a) : "l"(p));
    return a;
}
__device__ __forceinline__ void cp16(uint32_t dst, const void* src, int sz) {
    asm volatile("cp.async.cg.shared.global [%0], [%1], 16, %2;"
                 :: "r"(dst), "l"(src), "r"(sz) : "memory");
}
#define CP_COMMIT() asm volatile("cp.async.commit_group;" ::: "memory")
#define CP_WAIT(N)  asm volatile("cp.async.wait_group %0;" :: "n"(N) : "memory")

__device__ __forceinline__ void ldm_x4(uint32_t* r, uint32_t addr) {
    asm volatile("ldmatrix.sync.aligned.m8n8.x4.shared.b16 {%0,%1,%2,%3}, [%4];"
                 : "=r"(r[0]), "=r"(r[1]), "=r"(r[2]), "=r"(r[3]) : "r"(addr));
}
__device__ __forceinline__ void mma_s8(int* d, const uint32_t* a, uint32_t b0, uint32_t b1) {
    asm volatile("mma.sync.aligned.m16n8k32.row.col.s32.s8.s8.s32 "
                 "{%0,%1,%2,%3}, {%4,%5,%6,%7}, {%8,%9}, {%0,%1,%2,%3};"
                 : "+r"(d[0]), "+r"(d[1]), "+r"(d[2]), "+r"(d[3])
                 : "r"(a[0]), "r"(a[1]), "r"(a[2]), "r"(a[3]), "r"(b0), "r"(b1));
}

// ================= BN statistics: one block per channel ========================
__global__ void bn_stats_kernel(const float* __restrict__ x,
                                const float* __restrict__ gamma,
                                const float* __restrict__ beta,
                                float* __restrict__ scale,
                                float* __restrict__ shift)
{
    const int c = blockIdx.x;
    float s = 0.f, s2 = 0.f;
    for (int n = 0; n < NB; n++) {
        const float* p = x + ((size_t)n * CC + c) * HWH;
        for (int i = threadIdx.x; i < HWH; i += blockDim.x) {
            float v = p[i];
            s  += v;
            s2 += v * v;
        }
    }
    __shared__ float sh[512], sh2[512];
    sh[threadIdx.x]  = s;
    sh2[threadIdx.x] = s2;
    __syncthreads();
    for (int o = 256; o > 0; o >>= 1) {
        if (threadIdx.x < o) {
            sh[threadIdx.x]  += sh[threadIdx.x + o];
            sh2[threadIdx.x] += sh2[threadIdx.x + o];
        }
        __syncthreads();
    }
    if (threadIdx.x == 0) {
        const float inv_n = 1.0f / (float)((size_t)NB * HWH);
        float m   = sh[0] * inv_n;
        float var = sh2[0] * inv_n - m * m;
        float sc  = gamma[c] * rsqrtf(var + EPSV);
        scale[c] = sc;
        shift[c] = beta[c] - m * sc;
    }
}

// ============ weight prep: alpha[oc] + int8 sign pack, k = tap*256+ic ==========
__global__ void wprep_kernel(const float* __restrict__ w,
                             float* __restrict__ alpha,
                             signed char* __restrict__ w8)
{
    const int oc = blockIdx.x;
    const float* wp = w + (size_t)oc * KKT;     // [ic][ky][kx]

    float s = 0.f;
    for (int i = threadIdx.x; i < KKT; i += 256) s += fabsf(wp[i]);
    __shared__ float sh[256];
    sh[threadIdx.x] = s;
    __syncthreads();
    for (int o = 128; o > 0; o >>= 1) {
        if (threadIdx.x < o) sh[threadIdx.x] += sh[threadIdx.x + o];
        __syncthreads();
    }
    if (threadIdx.x == 0) alpha[oc] = sh[0] * (1.0f / (float)KKT);

    for (int k = threadIdx.x; k < KKT; k += 256) {
        const int tap = k >> 8;
        const int ic  = k & 255;
        float v = wp[ic * 9 + tap];
        w8[(size_t)oc * KKT + k] = (v > 0.f) ? 1 : -1;
    }
}

// ====== BN apply + int8 sign pack + channel mean. warp=32ch group x 32 pix =====
__global__ void bn_apply_pack_kernel(const float* __restrict__ x,
                                     const float* __restrict__ scale,
                                     const float* __restrict__ shift,
                                     signed char* __restrict__ act8,
                                     float* __restrict__ amean)
{
    const int lane = threadIdx.x & 31;
    const int wy   = threadIdx.x >> 5;        // channel group [32wy, 32wy+32)
    const int pix  = blockIdx.x * 32 + lane;
    const int n = pix / HWH;
    const int p = pix - n * HWH;

    const float* base = x + ((size_t)n * CC + wy * 32) * HWH + p;
    uint32_t wbuf[8];
    #pragma unroll
    for (int i = 0; i < 8; i++) wbuf[i] = 0;
    float s = 0.f;
    #pragma unroll
    for (int i = 0; i < 32; i++) {
        const int c = wy * 32 + i;
        float v = fmaf(base[(size_t)i * HWH], scale[c], shift[c]);
        s += v;
        uint32_t byte = (v > 0.f) ? 0x01u : 0xFFu;
        wbuf[i >> 2] |= byte << ((i & 3) * 8);
    }
    uint4* dst = (uint4*)(act8 + (size_t)pix * 256 + wy * 32);
    dst[0] = make_uint4(wbuf[0], wbuf[1], wbuf[2], wbuf[3]);
    dst[1] = make_uint4(wbuf[4], wbuf[5], wbuf[6], wbuf[7]);

    __shared__ float sh[8][32];
    sh[wy][lane] = s;
    __syncthreads();
    if (wy == 0) {
        float t = 0.f;
        #pragma unroll
        for (int k = 0; k < 8; k++) t += sh[k][lane];   // fixed order
        amean[pix] = t * (1.0f / 256.0f);
    }
}

// ================= 3x3 box filter / 9 with zero padding ========================
__global__ void box3_kernel(const float* __restrict__ a, float* __restrict__ K)
{
    const int idx = blockIdx.x * 256 + threadIdx.x;
    if (idx >= NPIX) return;
    const int n = idx / HWH;
    const int p = idx - n * HWH;
    const int h = p / WWD;
    const int w = p - h * WWD;
    const float* an = a + (size_t)n * HWH;
    float s = 0.f;
    #pragma unroll
    for (int dy = -1; dy <= 1; dy++) {
        int hh = h + dy;
        if (hh < 0 || hh >= HH) continue;
        #pragma unroll
        for (int dx = -1; dx <= 1; dx++) {
            int ww = w + dx;
            if (ww < 0 || ww >= WWD) continue;
            s += an[hh * WWD + ww];
        }
    }
    K[idx] = s * (1.0f / 9.0f);
}

// ========== binary conv via int8 mma.sync implicit GEMM, fused epilogue =========
// CTA: M=128 pixels x N=128 oc, K=2304 in 18 chunks of 128B.
// 2-stage cp.async pipeline; 8 warps, warp tile 32x64; smem XOR-swizzled for
// conflict-free ldmatrix.
template <bool FUSE_RES>
__global__ void __launch_bounds__(256, 1)
conv_mma_kernel(const signed char* __restrict__ act8,
                const signed char* __restrict__ w8,
                const float* __restrict__ alpha,
                const float* __restrict__ Ksc,
                const float* __restrict__ res,
                float* __restrict__ out)
{
    extern __shared__ char dsmem[];
    __shared__ float s_alpha[N_TILE];

    const int tid  = threadIdx.x;
    const int wid  = tid >> 5;
    const int lane = tid & 31;
    const int pix0 = blockIdx.x * M_TILE;
    const int ocbase = blockIdx.y * N_TILE;

    const int warpM = (wid & 3) * 32;         // 4 warps along M
    const int warpN = (wid >> 2) * 64;        // 2 warps along N

    const uint32_t sbase = smem_u32(dsmem);

    if (tid < N_TILE) s_alpha[tid] = alpha[ocbase + tid];

    int acc[2][8][4];
    #pragma unroll
    for (int mi = 0; mi < 2; mi++)
        #pragma unroll
        for (int ni = 0; ni < 8; ni++)
            #pragma unroll
            for (int q = 0; q < 4; q++) acc[mi][ni][q] = 0;

    // -------- chunk loader (cp.async, zero-fill for padding) --------
    auto load_chunk = [&](int c, int stage) {
        const int tap  = c >> 1;
        const int half = c & 1;
        const int dy = tap / 3 - 1;
        const int dx = tap % 3 - 1;
        const uint32_t aS = sbase + (uint32_t)stage * STAGE_BYTES;
        const uint32_t bS = aS + 16384;
        #pragma unroll
        for (int it = 0; it < 4; it++) {
            const int idx = tid + it * 256;
            const int row = idx >> 3, seg = idx & 7;
            const int pix = pix0 + row;
            const int n = pix / HWH;
            const int p = pix - n * HWH;
            const int h = p / WWD;
            const int w = p - h * WWD;
            const int hh = h + dy, ww = w + dx;
            const bool vld = (hh >= 0) & (hh < HH) & (ww >= 0) & (ww < WWD);
            const signed char* src = vld
                ? act8 + ((size_t)(n * HWH + hh * WWD + ww)) * 256 + half * 128 + seg * 16
                : act8;
            cp16(aS + row * 128 + ((seg ^ (row & 7)) << 4), src, vld ? 16 : 0);
        }
        #pragma unroll
        for (int it = 0; it < 4; it++) {
            const int idx = tid + it * 256;
            const int row = idx >> 3, seg = idx & 7;
            const signed char* src = w8 + (size_t)(ocbase + row) * KKT + c * 128 + seg * 16;
            cp16(bS + row * 128 + ((seg ^ (row & 7)) << 4), src, 16);
        }
        CP_COMMIT();
    };

    load_chunk(0, 0);

    for (int c = 0; c < NCHUNK; c++) {
        const int s = c & 1;
        if (c + 1 < NCHUNK) { load_chunk(c + 1, s ^ 1); CP_WAIT(1); }
        else                { CP_WAIT(0); }
        __syncthreads();

        const uint32_t aS = sbase + (uint32_t)s * STAGE_BYTES;
        const uint32_t bS = aS + 16384;
        const int rlo = lane & 15;
        const int hi  = (lane >> 4) & 1;

        #pragma unroll
        for (int k32 = 0; k32 < 4; k32++) {
            uint32_t afr[2][4];
            #pragma unroll
            for (int mi = 0; mi < 2; mi++) {
                const int row = warpM + mi * 16 + rlo;
                const uint32_t addr = aS + row * 128 + (((k32 * 2 + hi) ^ (row & 7)) << 4);
                ldm_x4(afr[mi], addr);
            }
            uint32_t bfr[4][4];
            #pragma unroll
            for (int g = 0; g < 4; g++) {
                const int row = warpN + g * 16 + rlo;
                const uint32_t addr = bS + row * 128 + (((k32 * 2 + hi) ^ (row & 7)) << 4);
                ldm_x4(bfr[g], addr);
            }
            #pragma unroll
            for (int mi = 0; mi < 2; mi++)
                #pragma unroll
                for (int ni = 0; ni < 8; ni++) {
                    const int g = ni >> 1, odd = ni & 1;
                    mma_s8(acc[mi][ni], afr[mi], bfr[g][odd], bfr[g][odd + 2]);
                }
        }
        __syncthreads();
    }

    // -------- epilogue: alpha[oc] * K[pix] * acc (+res), relu --------
    __syncthreads();   // s_alpha visible
    const int gID = lane >> 2, tID = lane & 3;
    #pragma unroll
    for (int mi = 0; mi < 2; mi++) {
        #pragma unroll
        for (int rr = 0; rr < 2; rr++) {
            const int pix = pix0 + warpM + mi * 16 + gID + rr * 8;
            const int n = pix / HWH;
            const int p = pix - n * HWH;
            const float kv = Ksc[pix];
            const size_t obase = (size_t)n * CC * HWH + p;
            #pragma unroll
            for (int ni = 0; ni < 8; ni++) {
                const int oc = warpN + ni * 8 + tID * 2;
                const float a0 = s_alpha[oc]     * kv;
                const float a1 = s_alpha[oc + 1] * kv;
                float v0 = a0 * (float)acc[mi][ni][rr * 2 + 0];
                float v1 = a1 * (float)acc[mi][ni][rr * 2 + 1];
                const size_t i0 = obase + (size_t)(ocbase + oc) * HWH;
                if (FUSE_RES) {
                    v0 += res[i0];
                    v1 += res[i0 + HWH];
                }
                out[i0]       = fmaxf(v0, 0.f);
                out[i0 + HWH] = fmaxf(v1, 0.f);
            }
        }
    }
}

// ================================ launcher =====================================
extern "C" void kernel_launch(void* const* d_in, const int* in_sizes, int n_in,
                              void* d_out, int out_size)
{
    (void)in_sizes; (void)n_in; (void)out_size;
    const float* x  = (const float*)d_in[0];
    const float* g1 = (const float*)d_in[1];
    const float* b1 = (const float*)d_in[2];
    const float* w1 = (const float*)d_in[3];
    const float* g2 = (const float*)d_in[4];
    const float* b2 = (const float*)d_in[5];
    const float* w2 = (const float*)d_in[6];
    float* out = (float*)d_out;

    signed char *act8, *w8;
    float *alpha, *a, *K, *s1, *h1, *s2, *h2, *r;
    cudaGetSymbolAddress((void**)&act8, g_act8);
    cudaGetSymbolAddress((void**)&w8,   g_w8);
    cudaGetSymbolAddress((void**)&alpha, g_alpha);
    cudaGetSymbolAddress((void**)&a,     g_a);
    cudaGetSymbolAddress((void**)&K,     g_K);
    cudaGetSymbolAddress((void**)&s1,    g_s1);
    cudaGetSymbolAddress((void**)&h1,    g_h1);
    cudaGetSymbolAddress((void**)&s2,    g_s2);
    cudaGetSymbolAddress((void**)&h2,    g_h2);
    cudaGetSymbolAddress((void**)&r,     g_r);

    cudaFuncSetAttribute(conv_mma_kernel<false>,
                         cudaFuncAttributeMaxDynamicSharedMemorySize, DSMEM_BYTES);
    cudaFuncSetAttribute(conv_mma_kernel<true>,
                         cudaFuncAttributeMaxDynamicSharedMemorySize, DSMEM_BYTES);

    const dim3 cgrid(NPIX / M_TILE, CC / N_TILE);   // (784, 2)

    // ---- stage 1: BN1 -> pack -> K1 -> mma conv1 (+ReLU) ----
    bn_stats_kernel<<<CC, 512>>>(x, g1, b1, s1, h1);
    wprep_kernel<<<CC, 256>>>(w1, alpha, w8);
    bn_apply_pack_kernel<<<NPIX / 32, 256>>>(x, s1, h1, act8, a);
    box3_kernel<<<(NPIX + 255) / 256, 256>>>(a, K);
    conv_mma_kernel<false><<<cgrid, 256, DSMEM_BYTES>>>(act8, w8, alpha, K, nullptr, r);

    // ---- stage 2: BN2 -> pack -> K2 -> mma conv2 + identity + ReLU ----
    bn_stats_kernel<<<CC, 512>>>(r, g2, b2, s2, h2);
    wprep_kernel<<<CC, 256>>>(w2, alpha, w8);
    bn_apply_pack_kernel<<<NPIX / 32, 256>>>(r, s2, h2, act8, a);
    box3_kernel<<<(NPIX + 255) / 256, 256>>>(a, K);
    conv_mma_kernel<true><<<cgrid, 256, DSMEM_BYTES>>>(act8, w8, alpha, K, x, out);
}

// round 12
// speedup vs baseline: 3.3484x; 3.3484x over previous
#include <cuda_runtime.h>
#include <cuda_bf16.h>
#include <cstdint>

#define NB    32
#define CC    256
#define HH    56
#define WWD   56
#define HWH   (HH*WWD)        /* 3136  */
#define NPIX  (NB*HWH)        /* 100352 */
#define KKT   2304            /* 256*9 */
#define EPSV  1e-5f
#define GRIDX (NPIX/64)       /* 1568 */

// ---------------- static device scratch (no allocations allowed) ----------------
__device__ uint32_t g_abits[NPIX * 8];        // packed sign bits, 8 words / pixel (3.2MB)
__device__ uint32_t g_wbits[CC * 72];         // packed weight bits, 72 words / oc
__device__ float    g_alpha[CC];
__device__ float    g_a[NPIX];                // channel mean per pixel
__device__ float    g_K[NPIX];                // 3x3 box of g_a / 9
__device__ float    g_s1[CC], g_h1[CC];       // bn1 scale / shift
__device__ float    g_s2[CC], g_h2[CC];       // bn2 scale / shift
__device__ float    g_p1[CC * GRIDX];         // bn2 partial sums   (1.6MB)
__device__ float    g_p2[CC * GRIDX];         // bn2 partial sumsq  (1.6MB)
__device__ float    g_r[(size_t)NPIX * CC];   // relu(conv1) fp32 (102.8 MB)

// ============== BN1 statistics: one block per channel, float4 + n-unroll =======
__global__ void bn_stats_kernel(const float* __restrict__ x,
                                const float* __restrict__ gamma,
                                const float* __restrict__ beta,
                                float* __restrict__ scale,
                                float* __restrict__ shift)
{
    const int c = blockIdx.x;
    float s = 0.f, s2 = 0.f;
    for (int n = 0; n < NB; n += 2) {
        const float4* pa = (const float4*)(x + ((size_t)n * CC + c) * HWH);
        const float4* pb = (const float4*)(x + ((size_t)(n + 1) * CC + c) * HWH);
        for (int i = threadIdx.x; i < HWH / 4; i += blockDim.x) {
            float4 va = pa[i], vb = pb[i];
            s  += (va.x + va.y) + (va.z + va.w) + (vb.x + vb.y) + (vb.z + vb.w);
            s2 += (va.x*va.x + va.y*va.y) + (va.z*va.z + va.w*va.w)
                + (vb.x*vb.x + vb.y*vb.y) + (vb.z*vb.z + vb.w*vb.w);
        }
    }
    __shared__ float sh[512], sh2[512];
    sh[threadIdx.x]  = s;
    sh2[threadIdx.x] = s2;
    __syncthreads();
    for (int o = 256; o > 0; o >>= 1) {
        if (threadIdx.x < o) {
            sh[threadIdx.x]  += sh[threadIdx.x + o];
            sh2[threadIdx.x] += sh2[threadIdx.x + o];
        }
        __syncthreads();
    }
    if (threadIdx.x == 0) {
        const float inv_n = 1.0f / (float)((size_t)NB * HWH);
        float m   = sh[0] * inv_n;
        float var = sh2[0] * inv_n - m * m;
        float sc  = gamma[c] * rsqrtf(var + EPSV);
        scale[c] = sc;
        shift[c] = beta[c] - m * sc;
    }
}

// ======== BN2 finalize from deterministic partials written by conv1 ============
__global__ void bn2_finalize_kernel(const float* __restrict__ p1,
                                    const float* __restrict__ p2,
                                    const float* __restrict__ gamma,
                                    const float* __restrict__ beta,
                                    float* __restrict__ scale,
                                    float* __restrict__ shift)
{
    const int c = blockIdx.x;
    float s = 0.f, s2 = 0.f;
    for (int i = threadIdx.x; i < GRIDX; i += 256) {
        s  += p1[c * GRIDX + i];
        s2 += p2[c * GRIDX + i];
    }
    __shared__ float sh[256], sh2[256];
    sh[threadIdx.x]  = s;
    sh2[threadIdx.x] = s2;
    __syncthreads();
    for (int o = 128; o > 0; o >>= 1) {
        if (threadIdx.x < o) {
            sh[threadIdx.x]  += sh[threadIdx.x + o];
            sh2[threadIdx.x] += sh2[threadIdx.x + o];
        }
        __syncthreads();
    }
    if (threadIdx.x == 0) {
        const float inv_n = 1.0f / (float)((size_t)NB * HWH);
        float m   = sh[0] * inv_n;
        float var = sh2[0] * inv_n - m * m;
        float sc  = gamma[c] * rsqrtf(var + EPSV);
        scale[c] = sc;
        shift[c] = beta[c] - m * sc;
    }
}

// ================= weight prep: alpha[oc] + bit pack ===========================
__global__ void wprep_kernel(const float* __restrict__ w,
                             float* __restrict__ alpha,
                             uint32_t* __restrict__ wbits)
{
    const int oc = blockIdx.x;
    const float* wp = w + (size_t)oc * KKT;   // [ic][ky][kx]

    float s = 0.f;
    for (int i = threadIdx.x; i < KKT; i += 256) s += fabsf(wp[i]);
    __shared__ float sh[256];
    sh[threadIdx.x] = s;
    __syncthreads();
    for (int o = 128; o > 0; o >>= 1) {
        if (threadIdx.x < o) sh[threadIdx.x] += sh[threadIdx.x + o];
        __syncthreads();
    }
    if (threadIdx.x == 0) alpha[oc] = sh[0] * (1.0f / (float)KKT);

    if (threadIdx.x < 72) {
        const int t  = threadIdx.x >> 3;   // tap 0..8 (ky*3+kx)
        const int wd = threadIdx.x & 7;    // word 0..7
        uint32_t bits = 0;
        #pragma unroll
        for (int b = 0; b < 32; b++) {
            int ch = wd * 32 + b;
            float v = wp[ch * 9 + t];
            bits |= (v > 0.f ? 1u : 0u) << b;
        }
        wbits[oc * 72 + t * 8 + wd] = bits;
    }
}

// ====== BN apply + sign-pack + channel mean. 8 warps x 32 lanes ================
__global__ void bn_apply_pack_kernel(const float* __restrict__ x,
                                     const float* __restrict__ scale,
                                     const float* __restrict__ shift,
                                     uint32_t* __restrict__ abits,
                                     float* __restrict__ amean)
{
    const int lane = threadIdx.x & 31;
    const int wy   = threadIdx.x >> 5;        // channels [32wy, 32wy+32)
    const int pix  = blockIdx.x * 32 + lane;
    const int n = pix / HWH;
    const int p = pix - n * HWH;

    const float* base = x + ((size_t)n * CC + wy * 32) * HWH + p;
    uint32_t bits = 0;
    float s = 0.f;
    #pragma unroll
    for (int i = 0; i < 32; i++) {
        const int c = wy * 32 + i;
        float v = fmaf(base[(size_t)i * HWH], scale[c], shift[c]);
        s += v;
        bits |= (v > 0.f ? 1u : 0u) << i;
    }
    abits[(size_t)pix * 8 + wy] = bits;

    __shared__ float sh[8][32];
    sh[wy][lane] = s;
    __syncthreads();
    if (wy == 0) {
        float t = 0.f;
        #pragma unroll
        for (int k = 0; k < 8; k++) t += sh[k][lane];   // fixed order
        amean[pix] = t * (1.0f / 256.0f);
    }
}

// ================= 3x3 box filter / 9 with zero padding ========================
__global__ void box3_kernel(const float* __restrict__ a, float* __restrict__ K)
{
    const int idx = blockIdx.x * 256 + threadIdx.x;
    if (idx >= NPIX) return;
    const int n = idx / HWH;
    const int p = idx - n * HWH;
    const int h = p / WWD;
    const int w = p - h * WWD;
    const float* an = a + (size_t)n * HWH;
    float s = 0.f;
    #pragma unroll
    for (int dy = -1; dy <= 1; dy++) {
        int hh = h + dy;
        if (hh < 0 || hh >= HH) continue;
        #pragma unroll
        for (int dx = -1; dx <= 1; dx++) {
            int ww = w + dx;
            if (ww < 0 || ww >= WWD) continue;
            s += an[hh * WWD + ww];
        }
    }
    K[idx] = s * (1.0f / 9.0f);
}

// ================= binary conv: XNOR-popcount, 2 pixels/thread =================
// grid: (NPIX/64, 4), block 256 = 8 warps. Warp wy -> oc [ocb+8wy, +8).
// Lane handles pixels (pix0+lane) and (pix0+32+lane); weight LDS amortized over
// both. Invalid taps: popcount computed on zero-filled words but accumulated
// through a validity mask (LOP3), so they contribute exactly 0 -- the R9 bug
// was accumulating popc(w) unmasked. Optional fused BN2 partial stats (conv1).
template <bool FUSE_RES, bool STATS>
__global__ void __launch_bounds__(256)
binconv_kernel(const uint32_t* __restrict__ abits,
               const uint32_t* __restrict__ wbits,
               const float*    __restrict__ alpha,
               const float*    __restrict__ Ksc,
               const float*    __restrict__ res,
               float*          __restrict__ out,
               float*          __restrict__ p1,
               float*          __restrict__ p2)
{
    __shared__ __align__(16) uint32_t ws[64 * 72];   // 18 KB
    __shared__ float sal[64];

    const int ocbase = blockIdx.y * 64;
    for (int i = threadIdx.x; i < 64 * 72; i += 256) ws[i] = wbits[ocbase * 72 + i];
    if (threadIdx.x < 64) sal[threadIdx.x] = alpha[ocbase + threadIdx.x];
    __syncthreads();

    const int lane = threadIdx.x & 31;
    const int wy   = threadIdx.x >> 5;
    const int pixA = blockIdx.x * 64 + lane;
    const int pixB = pixA + 32;
    const int n  = pixA / HWH;                 // 64 | 3136 -> same n for A,B
    const int pa = pixA - n * HWH;
    const int pb = pixB - n * HWH;
    const int hA = pa / WWD, wA = pa - hA * WWD;
    const int hB = pb / WWD, wB = pb - hB * WWD;
    const float kvA = Ksc[pixA];
    const float kvB = Ksc[pixB];

    int accA[8], accB[8];
    #pragma unroll
    for (int i = 0; i < 8; i++) { accA[i] = 0; accB[i] = 0; }
    int nvA = 0, nvB = 0;

    const uint32_t* wsp = ws + (wy * 8) * 72;
    const uint32_t* abase = abits + ((size_t)n * HWH) * 8;

    #pragma unroll 1
    for (int t = 0; t < 9; t++) {
        const int dy = t / 3 - 1;
        const int dx = t - 3 * (t / 3) - 1;
        const int hhA = hA + dy, wwA = wA + dx;
        const int hhB = hB + dy, wwB = wB + dx;
        const bool vA = (hhA >= 0) & (hhA < HH) & (wwA >= 0) & (wwA < WWD);
        const bool vB = (hhB >= 0) & (hhB < HH) & (wwB >= 0) & (wwB < WWD);
        const int mA = vA ? ~0 : 0;
        const int mB = vB ? ~0 : 0;
        uint4 a0A = make_uint4(0,0,0,0), a1A = a0A, a0B = a0A, a1B = a0A;
        if (vA) {
            const uint32_t* ap = abase + (size_t)(hhA * WWD + wwA) * 8;
            a0A = *(const uint4*)ap; a1A = *(const uint4*)(ap + 4);
            nvA++;
        }
        if (vB) {
            const uint32_t* ap = abase + (size_t)(hhB * WWD + wwB) * 8;
            a0B = *(const uint4*)ap; a1B = *(const uint4*)(ap + 4);
            nvB++;
        }
        #pragma unroll
        for (int i = 0; i < 8; i++) {
            const uint4 w0 = *(const uint4*)(wsp + i * 72 + t * 8);
            const uint4 w1 = *(const uint4*)(wsp + i * 72 + t * 8 + 4);
            const int pA = ((__popc(a0A.x ^ w0.x) + __popc(a0A.y ^ w0.y))
                          + (__popc(a0A.z ^ w0.z) + __popc(a0A.w ^ w0.w)))
                         + ((__popc(a1A.x ^ w1.x) + __popc(a1A.y ^ w1.y))
                          + (__popc(a1A.z ^ w1.z) + __popc(a1A.w ^ w1.w)));
            const int pB = ((__popc(a0B.x ^ w0.x) + __popc(a0B.y ^ w0.y))
                          + (__popc(a0B.z ^ w0.z) + __popc(a0B.w ^ w0.w)))
                         + ((__popc(a1B.x ^ w1.x) + __popc(a1B.y ^ w1.y))
                          + (__popc(a1B.z ^ w1.z) + __popc(a1B.w ^ w1.w)));
            accA[i] += pA & mA;    // invalid tap contributes exactly 0
            accB[i] += pB & mB;
        }
    }

    const size_t obaseA = (size_t)n * CC * HWH + pa;
    const size_t obaseB = (size_t)n * CC * HWH + pb;
    #pragma unroll
    for (int i = 0; i < 8; i++) {
        const int oc = ocbase + wy * 8 + i;
        const float al = sal[wy * 8 + i];
        float vA = al * kvA * (float)(256 * nvA - 2 * accA[i]);
        float vB = al * kvB * (float)(256 * nvB - 2 * accB[i]);
        const size_t iA = obaseA + (size_t)oc * HWH;
        const size_t iB = obaseB + (size_t)oc * HWH;
        if (FUSE_RES) { vA += res[iA]; vB += res[iB]; }
        vA = fmaxf(vA, 0.f);
        vB = fmaxf(vB, 0.f);
        out[iA] = vA;
        out[iB] = vB;
        if (STATS) {
            float sv = vA + vB;
            float sq = vA * vA + vB * vB;
            #pragma unroll
            for (int o = 16; o > 0; o >>= 1) {
                sv += __shfl_xor_sync(0xffffffffu, sv, o);
                sq += __shfl_xor_sync(0xffffffffu, sq, o);
            }
            if (lane == 0) {
                p1[(size_t)oc * GRIDX + blockIdx.x] = sv;
                p2[(size_t)oc * GRIDX + blockIdx.x] = sq;
            }
        }
    }
}

// ================================ launcher =====================================
extern "C" void kernel_launch(void* const* d_in, const int* in_sizes, int n_in,
                              void* d_out, int out_size)
{
    (void)in_sizes; (void)n_in; (void)out_size;
    const float* x  = (const float*)d_in[0];
    const float* g1 = (const float*)d_in[1];
    const float* b1 = (const float*)d_in[2];
    const float* w1 = (const float*)d_in[3];
    const float* g2 = (const float*)d_in[4];
    const float* b2 = (const float*)d_in[5];
    const float* w2 = (const float*)d_in[6];
    float* out = (float*)d_out;

    uint32_t *abits, *wbits;
    float *alpha, *a, *K, *s1, *h1, *s2, *h2, *r, *p1, *p2;
    cudaGetSymbolAddress((void**)&abits, g_abits);
    cudaGetSymbolAddress((void**)&wbits, g_wbits);
    cudaGetSymbolAddress((void**)&alpha, g_alpha);
    cudaGetSymbolAddress((void**)&a,     g_a);
    cudaGetSymbolAddress((void**)&K,     g_K);
    cudaGetSymbolAddress((void**)&s1,    g_s1);
    cudaGetSymbolAddress((void**)&h1,    g_h1);
    cudaGetSymbolAddress((void**)&s2,    g_s2);
    cudaGetSymbolAddress((void**)&h2,    g_h2);
    cudaGetSymbolAddress((void**)&r,     g_r);
    cudaGetSymbolAddress((void**)&p1,    g_p1);
    cudaGetSymbolAddress((void**)&p2,    g_p2);

    const dim3 cgrid(GRIDX, 4);

    // ---- stage 1: BN1 -> pack -> K1 -> binary conv1 (+ReLU, +BN2 partials) ----
    bn_stats_kernel<<<CC, 512>>>(x, g1, b1, s1, h1);
    wprep_kernel<<<CC, 256>>>(w1, alpha, wbits);
    bn_apply_pack_kernel<<<NPIX / 32, 256>>>(x, s1, h1, abits, a);
    box3_kernel<<<(NPIX + 255) / 256, 256>>>(a, K);
    binconv_kernel<false, true><<<cgrid, 256>>>(abits, wbits, alpha, K, nullptr, r, p1, p2);

    // ---- stage 2: BN2(finalize) -> pack -> K2 -> conv2 + identity + ReLU ----
    bn2_finalize_kernel<<<CC, 256>>>(p1, p2, g2, b2, s2, h2);
    wprep_kernel<<<CC, 256>>>(w2, alpha, wbits);
    bn_apply_pack_kernel<<<NPIX / 32, 256>>>(r, s2, h2, abits, a);
    box3_kernel<<<(NPIX + 255) / 256, 256>>>(a, K);
    binconv_kernel<true, false><<<cgrid, 256>>>(abits, wbits, alpha, K, x, out, p1, p2);
}

// round 13
// speedup vs baseline: 3.4431x; 1.0283x over previous
#include <cuda_runtime.h>
#include <cuda_bf16.h>
#include <cstdint>

#define NB    32
#define CC    256
#define HH    56
#define WWD   56
#define HWH   (HH*WWD)        /* 3136  */
#define NPIX  (NB*HWH)        /* 100352 */
#define KKT   2304            /* 256*9 */
#define EPSV  1e-5f
#define GRIDX (NPIX/64)       /* 1568 */
#define PW    58              /* padded width  */
#define PIMG  (PW*PW)         /* 3364 padded px per image */

// ---------------- static device scratch (no allocations allowed) ----------------
// Padded activation bits: one zero guard ring per image. __device__ globals are
// zero-initialized at module load; guard cells are NEVER written, so every tap
// read is unconditionally in-bounds and guards contribute popc(w) (corrected in
// the epilogue).
__device__ uint32_t g_abits[NB * PIMG * 8];   // 3.44 MB
__device__ uint32_t g_wbits[CC * 72];         // packed weight bits, 72 words / oc
__device__ int      g_corr[CC * 9];           // 256 - 2*popc(weights of tap)
__device__ float    g_alpha[CC];
__device__ float    g_a[NPIX];                // channel mean per pixel
__device__ float    g_K[NPIX];                // 3x3 box of g_a / 9
__device__ float    g_s1[CC], g_h1[CC];       // bn1 scale / shift
__device__ float    g_s2[CC], g_h2[CC];       // bn2 scale / shift
__device__ float    g_p1[CC * GRIDX];         // bn2 partial sums   (1.6MB)
__device__ float    g_p2[CC * GRIDX];         // bn2 partial sumsq  (1.6MB)
__device__ float    g_r[(size_t)NPIX * CC];   // relu(conv1) fp32 (102.8 MB)

// ============== BN1 statistics: one block per channel, float4 + n-unroll =======
__global__ void bn_stats_kernel(const float* __restrict__ x,
                                const float* __restrict__ gamma,
                                const float* __restrict__ beta,
                                float* __restrict__ scale,
                                float* __restrict__ shift)
{
    const int c = blockIdx.x;
    float s = 0.f, s2 = 0.f;
    for (int n = 0; n < NB; n += 2) {
        const float4* pa = (const float4*)(x + ((size_t)n * CC + c) * HWH);
        const float4* pb = (const float4*)(x + ((size_t)(n + 1) * CC + c) * HWH);
        for (int i = threadIdx.x; i < HWH / 4; i += blockDim.x) {
            float4 va = pa[i], vb = pb[i];
            s  += (va.x + va.y) + (va.z + va.w) + (vb.x + vb.y) + (vb.z + vb.w);
            s2 += (va.x*va.x + va.y*va.y) + (va.z*va.z + va.w*va.w)
                + (vb.x*vb.x + vb.y*vb.y) + (vb.z*vb.z + vb.w*vb.w);
        }
    }
    __shared__ float sh[512], sh2[512];
    sh[threadIdx.x]  = s;
    sh2[threadIdx.x] = s2;
    __syncthreads();
    for (int o = 256; o > 0; o >>= 1) {
        if (threadIdx.x < o) {
            sh[threadIdx.x]  += sh[threadIdx.x + o];
            sh2[threadIdx.x] += sh2[threadIdx.x + o];
        }
        __syncthreads();
    }
    if (threadIdx.x == 0) {
        const float inv_n = 1.0f / (float)((size_t)NB * HWH);
        float m   = sh[0] * inv_n;
        float var = sh2[0] * inv_n - m * m;
        float sc  = gamma[c] * rsqrtf(var + EPSV);
        scale[c] = sc;
        shift[c] = beta[c] - m * sc;
    }
}

// ======== BN2 finalize from deterministic partials written by conv1 ============
__global__ void bn2_finalize_kernel(const float* __restrict__ p1,
                                    const float* __restrict__ p2,
                                    const float* __restrict__ gamma,
                                    const float* __restrict__ beta,
                                    float* __restrict__ scale,
                                    float* __restrict__ shift)
{
    const int c = blockIdx.x;
    float s = 0.f, s2 = 0.f;
    for (int i = threadIdx.x; i < GRIDX; i += 256) {
        s  += p1[c * GRIDX + i];
        s2 += p2[c * GRIDX + i];
    }
    __shared__ float sh[256], sh2[256];
    sh[threadIdx.x]  = s;
    sh2[threadIdx.x] = s2;
    __syncthreads();
    for (int o = 128; o > 0; o >>= 1) {
        if (threadIdx.x < o) {
            sh[threadIdx.x]  += sh[threadIdx.x + o];
            sh2[threadIdx.x] += sh2[threadIdx.x + o];
        }
        __syncthreads();
    }
    if (threadIdx.x == 0) {
        const float inv_n = 1.0f / (float)((size_t)NB * HWH);
        float m   = sh[0] * inv_n;
        float var = sh2[0] * inv_n - m * m;
        float sc  = gamma[c] * rsqrtf(var + EPSV);
        scale[c] = sc;
        shift[c] = beta[c] - m * sc;
    }
}

// ======= weight prep: alpha[oc] + bit pack + per-tap popcount correction =======
__global__ void wprep_kernel(const float* __restrict__ w,
                             float* __restrict__ alpha,
                             uint32_t* __restrict__ wbits,
                             int* __restrict__ corr)
{
    const int oc = blockIdx.x;
    const float* wp = w + (size_t)oc * KKT;   // [ic][ky][kx]

    float s = 0.f;
    for (int i = threadIdx.x; i < KKT; i += 256) s += fabsf(wp[i]);
    __shared__ float sh[256];
    __shared__ int   spc[72];
    sh[threadIdx.x] = s;
    __syncthreads();
    for (int o = 128; o > 0; o >>= 1) {
        if (threadIdx.x < o) sh[threadIdx.x] += sh[threadIdx.x + o];
        __syncthreads();
    }
    if (threadIdx.x == 0) alpha[oc] = sh[0] * (1.0f / (float)KKT);

    if (threadIdx.x < 72) {
        const int t  = threadIdx.x >> 3;   // tap 0..8 (ky*3+kx)
        const int wd = threadIdx.x & 7;    // word 0..7
        uint32_t bits = 0;
        #pragma unroll
        for (int b = 0; b < 32; b++) {
            int ch = wd * 32 + b;
            float v = wp[ch * 9 + t];
            bits |= (v > 0.f ? 1u : 0u) << b;
        }
        wbits[oc * 72 + t * 8 + wd] = bits;
        spc[threadIdx.x] = __popc(bits);
    }
    __syncthreads();
    if (threadIdx.x < 9) {
        int pc = 0;
        #pragma unroll
        for (int wd = 0; wd < 8; wd++) pc += spc[threadIdx.x * 8 + wd];
        corr[oc * 9 + threadIdx.x] = 256 - 2 * pc;   // guard-tap contribution
    }
}

// ====== BN apply + sign-pack (padded layout) + channel mean ====================
__global__ void bn_apply_pack_kernel(const float* __restrict__ x,
                                     const float* __restrict__ scale,
                                     const float* __restrict__ shift,
                                     uint32_t* __restrict__ abits,
                                     float* __restrict__ amean)
{
    const int lane = threadIdx.x & 31;
    const int wy   = threadIdx.x >> 5;        // channels [32wy, 32wy+32)
    const int pix  = blockIdx.x * 32 + lane;
    const int n = pix / HWH;
    const int p = pix - n * HWH;
    const int h = p / WWD;
    const int w = p - h * WWD;

    const float* base = x + ((size_t)n * CC + wy * 32) * HWH + p;
    uint32_t bits = 0;
    float s = 0.f;
    #pragma unroll
    for (int i = 0; i < 32; i++) {
        const int c = wy * 32 + i;
        float v = fmaf(base[(size_t)i * HWH], scale[c], shift[c]);
        s += v;
        bits |= (v > 0.f ? 1u : 0u) << i;
    }
    abits[((size_t)n * PIMG + (h + 1) * PW + (w + 1)) * 8 + wy] = bits;

    __shared__ float sh[8][32];
    sh[wy][lane] = s;
    __syncthreads();
    if (wy == 0) {
        float t = 0.f;
        #pragma unroll
        for (int k = 0; k < 8; k++) t += sh[k][lane];   // fixed order
        amean[pix] = t * (1.0f / 256.0f);
    }
}

// ================= 3x3 box filter / 9 with zero padding ========================
__global__ void box3_kernel(const float* __restrict__ a, float* __restrict__ K)
{
    const int idx = blockIdx.x * 256 + threadIdx.x;
    if (idx >= NPIX) return;
    const int n = idx / HWH;
    const int p = idx - n * HWH;
    const int h = p / WWD;
    const int w = p - h * WWD;
    const float* an = a + (size_t)n * HWH;
    float s = 0.f;
    #pragma unroll
    for (int dy = -1; dy <= 1; dy++) {
        int hh = h + dy;
        if (hh < 0 || hh >= HH) continue;
        #pragma unroll
        for (int dx = -1; dx <= 1; dx++) {
            int ww = w + dx;
            if (ww < 0 || ww >= WWD) continue;
            s += an[hh * WWD + ww];
        }
    }
    K[idx] = s * (1.0f / 9.0f);
}

// ================= binary conv: XNOR-popcount, guard-padded ====================
// grid (NPIX/64, 4), block 256 = 8 warps; warp wy -> oc [ocb+8wy,+8), lane ->
// pixels (pix0+lane, pix0+32+lane). Guard padding makes every tap read valid
// with COMPILE-TIME immediate offsets: hot loop = pure LDG/LDS/XOR/POPC/IADD3.
// Guard taps (act word = 0) contribute popc(w); removed exactly in the epilogue
// via per-(oc,tap) integer corrections for boundary pixels.
template <bool FUSE_RES, bool STATS>
__global__ void __launch_bounds__(256)
binconv_kernel(const uint32_t* __restrict__ abits,
               const uint32_t* __restrict__ wbits,
               const int*      __restrict__ corr,
               const float*    __restrict__ alpha,
               const float*    __restrict__ Ksc,
               const float*    __restrict__ res,
               float*          __restrict__ out,
               float*          __restrict__ p1,
               float*          __restrict__ p2)
{
    __shared__ __align__(16) uint32_t ws[64 * 72];   // 18 KB
    __shared__ int   scorr[64 * 9];                  // 2.25 KB
    __shared__ float sal[64];

    const int ocbase = blockIdx.y * 64;
    for (int i = threadIdx.x; i < 64 * 72; i += 256) ws[i] = wbits[ocbase * 72 + i];
    for (int i = threadIdx.x; i < 64 * 9; i += 256)  scorr[i] = corr[ocbase * 9 + i];
    if (threadIdx.x < 64) sal[threadIdx.x] = alpha[ocbase + threadIdx.x];
    __syncthreads();

    const int lane = threadIdx.x & 31;
    const int wy   = threadIdx.x >> 5;
    const int pixA = blockIdx.x * 64 + lane;
    const int pixB = pixA + 32;
    const int n  = pixA / HWH;                 // 64 | 3136 -> same n for A,B
    const int pa = pixA - n * HWH;
    const int pb = pixB - n * HWH;
    const int hA = pa / WWD, wA = pa - hA * WWD;
    const int hB = pb / WWD, wB = pb - hB * WWD;
    const float kvA = Ksc[pixA];
    const float kvB = Ksc[pixB];

    const uint32_t* pAb = abits + ((size_t)n * PIMG + (hA + 1) * PW + (wA + 1)) * 8;
    const uint32_t* pBb = abits + ((size_t)n * PIMG + (hB + 1) * PW + (wB + 1)) * 8;

    int accA[8], accB[8];
    #pragma unroll
    for (int i = 0; i < 8; i++) { accA[i] = 0; accB[i] = 0; }

    const uint32_t* wsp = ws + (wy * 8) * 72;

    // tap offsets in words (compile-time constants under full unroll)
    uint4 a0A = *(const uint4*)(pAb + (-PW - 1) * 8);
    uint4 a1A = *(const uint4*)(pAb + (-PW - 1) * 8 + 4);
    uint4 a0B = *(const uint4*)(pBb + (-PW - 1) * 8);
    uint4 a1B = *(const uint4*)(pBb + (-PW - 1) * 8 + 4);

    #pragma unroll
    for (int t = 0; t < 9; t++) {
        uint4 n0A, n1A, n0B, n1B;
        if (t < 8) {
            const int tn = t + 1;
            const int off = ((tn / 3 - 1) * PW + (tn % 3 - 1)) * 8;   // constant
            n0A = *(const uint4*)(pAb + off);
            n1A = *(const uint4*)(pAb + off + 4);
            n0B = *(const uint4*)(pBb + off);
            n1B = *(const uint4*)(pBb + off + 4);
        }
        const uint32_t* wt = wsp + t * 8;
        #pragma unroll
        for (int i = 0; i < 8; i++) {
            const uint4 w0 = *(const uint4*)(wt + i * 72);
            const uint4 w1 = *(const uint4*)(wt + i * 72 + 4);
            accA[i] += ((__popc(a0A.x ^ w0.x) + __popc(a0A.y ^ w0.y))
                      + (__popc(a0A.z ^ w0.z) + __popc(a0A.w ^ w0.w)))
                     + ((__popc(a1A.x ^ w1.x) + __popc(a1A.y ^ w1.y))
                      + (__popc(a1A.z ^ w1.z) + __popc(a1A.w ^ w1.w)));
            accB[i] += ((__popc(a0B.x ^ w0.x) + __popc(a0B.y ^ w0.y))
                      + (__popc(a0B.z ^ w0.z) + __popc(a0B.w ^ w0.w)))
                     + ((__popc(a1B.x ^ w1.x) + __popc(a1B.y ^ w1.y))
                      + (__popc(a1B.z ^ w1.z) + __popc(a1B.w ^ w1.w)));
        }
        if (t < 8) { a0A = n0A; a1A = n1A; a0B = n0B; a1B = n1B; }
    }

    // ---- boundary corrections (exact): remove guard-tap popc(w) terms ----
    const unsigned mA = (hA == 0 ? 0x007u : 0u) | (hA == HH - 1 ? 0x1C0u : 0u)
                      | (wA == 0 ? 0x049u : 0u) | (wA == WWD - 1 ? 0x124u : 0u);
    const unsigned mB = (hB == 0 ? 0x007u : 0u) | (hB == HH - 1 ? 0x1C0u : 0u)
                      | (wB == 0 ? 0x049u : 0u) | (wB == WWD - 1 ? 0x124u : 0u);
    int corA[8], corB[8];
    #pragma unroll
    for (int i = 0; i < 8; i++) { corA[i] = 0; corB[i] = 0; }
    if (mA | mB) {
        #pragma unroll
        for (int t = 0; t < 9; t++) {
            const int* cp = scorr + (wy * 8) * 9 + t;
            if ((mA >> t) & 1) {
                #pragma unroll
                for (int i = 0; i < 8; i++) corA[i] += cp[i * 9];
            }
            if ((mB >> t) & 1) {
                #pragma unroll
                for (int i = 0; i < 8; i++) corB[i] += cp[i * 9];
            }
        }
    }

    const size_t obaseA = (size_t)n * CC * HWH + pa;
    const size_t obaseB = (size_t)n * CC * HWH + pb;
    #pragma unroll
    for (int i = 0; i < 8; i++) {
        const int oc = ocbase + wy * 8 + i;
        const float al = sal[wy * 8 + i];
        float vA = al * kvA * (float)(KKT - 2 * accA[i] - corA[i]);
        float vB = al * kvB * (float)(KKT - 2 * accB[i] - corB[i]);
        const size_t iA = obaseA + (size_t)oc * HWH;
        const size_t iB = obaseB + (size_t)oc * HWH;
        if (FUSE_RES) { vA += res[iA]; vB += res[iB]; }
        vA = fmaxf(vA, 0.f);
        vB = fmaxf(vB, 0.f);
        out[iA] = vA;
        out[iB] = vB;
        if (STATS) {
            float sv = vA + vB;
            float sq = vA * vA + vB * vB;
            #pragma unroll
            for (int o = 16; o > 0; o >>= 1) {
                sv += __shfl_xor_sync(0xffffffffu, sv, o);
                sq += __shfl_xor_sync(0xffffffffu, sq, o);
            }
            if (lane == 0) {
                p1[(size_t)oc * GRIDX + blockIdx.x] = sv;
                p2[(size_t)oc * GRIDX + blockIdx.x] = sq;
            }
        }
    }
}

// ================================ launcher =====================================
extern "C" void kernel_launch(void* const* d_in, const int* in_sizes, int n_in,
                              void* d_out, int out_size)
{
    (void)in_sizes; (void)n_in; (void)out_size;
    const float* x  = (const float*)d_in[0];
    const float* g1 = (const float*)d_in[1];
    const float* b1 = (const float*)d_in[2];
    const float* w1 = (const float*)d_in[3];
    const float* g2 = (const float*)d_in[4];
    const float* b2 = (const float*)d_in[5];
    const float* w2 = (const float*)d_in[6];
    float* out = (float*)d_out;

    uint32_t *abits, *wbits;
    int *corr;
    float *alpha, *a, *K, *s1, *h1, *s2, *h2, *r, *p1, *p2;
    cudaGetSymbolAddress((void**)&abits, g_abits);
    cudaGetSymbolAddress((void**)&wbits, g_wbits);
    cudaGetSymbolAddress((void**)&corr,  g_corr);
    cudaGetSymbolAddress((void**)&alpha, g_alpha);
    cudaGetSymbolAddress((void**)&a,     g_a);
    cudaGetSymbolAddress((void**)&K,     g_K);
    cudaGetSymbolAddress((void**)&s1,    g_s1);
    cudaGetSymbolAddress((void**)&h1,    g_h1);
    cudaGetSymbolAddress((void**)&s2,    g_s2);
    cudaGetSymbolAddress((void**)&h2,    g_h2);
    cudaGetSymbolAddress((void**)&r,     g_r);
    cudaGetSymbolAddress((void**)&p1,    g_p1);
    cudaGetSymbolAddress((void**)&p2,    g_p2);

    const dim3 cgrid(GRIDX, 4);

    // ---- stage 1: BN1 -> pack -> K1 -> binary conv1 (+ReLU, +BN2 partials) ----
    bn_stats_kernel<<<CC, 512>>>(x, g1, b1, s1, h1);
    wprep_kernel<<<CC, 256>>>(w1, alpha, wbits, corr);
    bn_apply_pack_kernel<<<NPIX / 32, 256>>>(x, s1, h1, abits, a);
    box3_kernel<<<(NPIX + 255) / 256, 256>>>(a, K);
    binconv_kernel<false, true><<<cgrid, 256>>>(abits, wbits, corr, alpha, K, nullptr, r, p1, p2);

    // ---- stage 2: BN2(finalize) -> pack -> K2 -> conv2 + identity + ReLU ----
    bn2_finalize_kernel<<<CC, 256>>>(p1, p2, g2, b2, s2, h2);
    wprep_kernel<<<CC, 256>>>(w2, alpha, wbits, corr);
    bn_apply_pack_kernel<<<NPIX / 32, 256>>>(r, s2, h2, abits, a);
    box3_kernel<<<(NPIX + 255) / 256, 256>>>(a, K);
    binconv_kernel<true, false><<<cgrid, 256>>>(abits, wbits, corr, alpha, K, x, out, p1, p2);
}

// round 14
// speedup vs baseline: 3.4782x; 1.0102x over previous
#include <cuda_runtime.h>
#include <cstdint>

#define NB    32
#define CC    256
#define HH    56
#define WWD   56
#define HWH   (HH*WWD)        /* 3136  */
#define NPIX  (NB*HWH)        /* 100352 */
#define KKT   2304            /* 256*9 */
#define EPSV  1e-5f
#define GRIDX (NPIX/64)       /* 1568 */
#define PW    58              /* padded width  */
#define PIMG  (PW*PW)         /* 3364 padded px per image */

// ---------------- static device scratch (no allocations allowed) ----------------
// Padded activation bits: one zero guard ring per image. __device__ globals are
// zero-initialized at module load; guard cells are NEVER written, so every tap
// read is unconditionally in-bounds; guard taps contribute popc(w), removed
// exactly in the epilogue via per-(oc,tap) corrections.
__device__ uint32_t g_abits[NB * PIMG * 8];   // 3.44 MB
__device__ uint32_t g_wbits[CC * 72];         // packed weight bits, 72 words / oc
__device__ int      g_corr[CC * 9];           // 256 - 2*popc(weights of tap)
__device__ float    g_alpha[CC];
__device__ float    g_a[NPIX];                // channel mean per pixel
__device__ float    g_K[NPIX];                // 3x3 box of g_a / 9
__device__ float    g_s1[CC], g_h1[CC];       // bn1 scale / shift
__device__ float    g_s2[CC], g_h2[CC];       // bn2 scale / shift
__device__ float    g_p1[CC * GRIDX];         // bn2 partial sums   (1.6MB)
__device__ float    g_p2[CC * GRIDX];         // bn2 partial sumsq  (1.6MB)
__device__ float    g_r[(size_t)NPIX * CC];   // relu(conv1) fp32 (102.8 MB)

// ============== BN1 statistics: one block per channel, float4 + n-unroll =======
__global__ void bn_stats_kernel(const float* __restrict__ x,
                                const float* __restrict__ gamma,
                                const float* __restrict__ beta,
                                float* __restrict__ scale,
                                float* __restrict__ shift)
{
    const int c = blockIdx.x;
    float s = 0.f, s2 = 0.f;
    for (int n = 0; n < NB; n += 2) {
        const float4* pa = (const float4*)(x + ((size_t)n * CC + c) * HWH);
        const float4* pb = (const float4*)(x + ((size_t)(n + 1) * CC + c) * HWH);
        for (int i = threadIdx.x; i < HWH / 4; i += blockDim.x) {
            float4 va = pa[i], vb = pb[i];
            s  += (va.x + va.y) + (va.z + va.w) + (vb.x + vb.y) + (vb.z + vb.w);
            s2 += (va.x*va.x + va.y*va.y) + (va.z*va.z + va.w*va.w)
                + (vb.x*vb.x + vb.y*vb.y) + (vb.z*vb.z + vb.w*vb.w);
        }
    }
    __shared__ float sh[512], sh2[512];
    sh[threadIdx.x]  = s;
    sh2[threadIdx.x] = s2;
    __syncthreads();
    for (int o = 256; o > 0; o >>= 1) {
        if (threadIdx.x < o) {
            sh[threadIdx.x]  += sh[threadIdx.x + o];
            sh2[threadIdx.x] += sh2[threadIdx.x + o];
        }
        __syncthreads();
    }
    if (threadIdx.x == 0) {
        const float inv_n = 1.0f / (float)((size_t)NB * HWH);
        float m   = sh[0] * inv_n;
        float var = sh2[0] * inv_n - m * m;
        float sc  = gamma[c] * rsqrtf(var + EPSV);
        scale[c] = sc;
        shift[c] = beta[c] - m * sc;
    }
}

// ======== BN2 finalize from deterministic partials written by conv1 ============
__global__ void bn2_finalize_kernel(const float* __restrict__ p1,
                                    const float* __restrict__ p2,
                                    const float* __restrict__ gamma,
                                    const float* __restrict__ beta,
                                    float* __restrict__ scale,
                                    float* __restrict__ shift)
{
    const int c = blockIdx.x;
    float s = 0.f, s2 = 0.f;
    for (int i = threadIdx.x; i < GRIDX; i += 256) {
        s  += p1[c * GRIDX + i];
        s2 += p2[c * GRIDX + i];
    }
    __shared__ float sh[256], sh2[256];
    sh[threadIdx.x]  = s;
    sh2[threadIdx.x] = s2;
    __syncthreads();
    for (int o = 128; o > 0; o >>= 1) {
        if (threadIdx.x < o) {
            sh[threadIdx.x]  += sh[threadIdx.x + o];
            sh2[threadIdx.x] += sh2[threadIdx.x + o];
        }
        __syncthreads();
    }
    if (threadIdx.x == 0) {
        const float inv_n = 1.0f / (float)((size_t)NB * HWH);
        float m   = sh[0] * inv_n;
        float var = sh2[0] * inv_n - m * m;
        float sc  = gamma[c] * rsqrtf(var + EPSV);
        scale[c] = sc;
        shift[c] = beta[c] - m * sc;
    }
}

// ======= weight prep: alpha[oc] + bit pack + per-tap popcount correction =======
__global__ void wprep_kernel(const float* __restrict__ w,
                             float* __restrict__ alpha,
                             uint32_t* __restrict__ wbits,
                             int* __restrict__ corr)
{
    const int oc = blockIdx.x;
    const float* wp = w + (size_t)oc * KKT;   // [ic][ky][kx]

    float s = 0.f;
    for (int i = threadIdx.x; i < KKT; i += 256) s += fabsf(wp[i]);
    __shared__ float sh[256];
    __shared__ int   spc[72];
    sh[threadIdx.x] = s;
    __syncthreads();
    for (int o = 128; o > 0; o >>= 1) {
        if (threadIdx.x < o) sh[threadIdx.x] += sh[threadIdx.x + o];
        __syncthreads();
    }
    if (threadIdx.x == 0) alpha[oc] = sh[0] * (1.0f / (float)KKT);

    if (threadIdx.x < 72) {
        const int t  = threadIdx.x >> 3;   // tap 0..8 (ky*3+kx)
        const int wd = threadIdx.x & 7;    // word 0..7
        uint32_t bits = 0;
        #pragma unroll
        for (int b = 0; b < 32; b++) {
            int ch = wd * 32 + b;
            float v = wp[ch * 9 + t];
            bits |= (v > 0.f ? 1u : 0u) << b;
        }
        wbits[oc * 72 + t * 8 + wd] = bits;
        spc[threadIdx.x] = __popc(bits);
    }
    __syncthreads();
    if (threadIdx.x < 9) {
        int pc = 0;
        #pragma unroll
        for (int wd = 0; wd < 8; wd++) pc += spc[threadIdx.x * 8 + wd];
        corr[oc * 9 + threadIdx.x] = 256 - 2 * pc;   // guard-tap contribution
    }
}

// ====== BN apply + sign-pack (padded layout) + channel mean ====================
__global__ void bn_apply_pack_kernel(const float* __restrict__ x,
                                     const float* __restrict__ scale,
                                     const float* __restrict__ shift,
                                     uint32_t* __restrict__ abits,
                                     float* __restrict__ amean)
{
    const int lane = threadIdx.x & 31;
    const int wy   = threadIdx.x >> 5;        // channels [32wy, 32wy+32)
    const int pix  = blockIdx.x * 32 + lane;
    const int n = pix / HWH;
    const int p = pix - n * HWH;
    const int h = p / WWD;
    const int w = p - h * WWD;

    const float* base = x + ((size_t)n * CC + wy * 32) * HWH + p;
    uint32_t bits = 0;
    float s = 0.f;
    #pragma unroll
    for (int i = 0; i < 32; i++) {
        const int c = wy * 32 + i;
        float v = fmaf(base[(size_t)i * HWH], scale[c], shift[c]);
        s += v;
        bits |= (v > 0.f ? 1u : 0u) << i;
    }
    abits[((size_t)n * PIMG + (h + 1) * PW + (w + 1)) * 8 + wy] = bits;

    __shared__ float sh[8][32];
    sh[wy][lane] = s;
    __syncthreads();
    if (wy == 0) {
        float t = 0.f;
        #pragma unroll
        for (int k = 0; k < 8; k++) t += sh[k][lane];   // fixed order
        amean[pix] = t * (1.0f / 256.0f);
    }
}

// ================= 3x3 box filter / 9 with zero padding ========================
__global__ void box3_kernel(const float* __restrict__ a, float* __restrict__ K)
{
    const int idx = blockIdx.x * 256 + threadIdx.x;
    if (idx >= NPIX) return;
    const int n = idx / HWH;
    const int p = idx - n * HWH;
    const int h = p / WWD;
    const int w = p - h * WWD;
    const float* an = a + (size_t)n * HWH;
    float s = 0.f;
    #pragma unroll
    for (int dy = -1; dy <= 1; dy++) {
        int hh = h + dy;
        if (hh < 0 || hh >= HH) continue;
        #pragma unroll
        for (int dx = -1; dx <= 1; dx++) {
            int ww = w + dx;
            if (ww < 0 || ww >= WWD) continue;
            s += an[hh * WWD + ww];
        }
    }
    K[idx] = s * (1.0f / 9.0f);
}

// ================= binary conv: XNOR-popcount, smem-staged activations =========
// grid (NPIX/64, 4), block 256 = 8 warps; warp wy -> oc [ocb+8wy,+8), lane ->
// pixels (pix0+lane, pix0+32+lane). The block's activation footprint is EXACTLY
// 4 consecutive padded rows (contiguous in gmem) = 7.4KB, loaded cooperatively
// ONCE into smem (previously each of 8 warps re-read it through L1 with 8
// wavefronts per LDG.128 due to the 32B pixel stride). Hot loop is LDS + pure
// XOR/POPC/IADD with compile-time tap offsets.
template <bool FUSE_RES, bool STATS>
__global__ void __launch_bounds__(256)
binconv_kernel(const uint32_t* __restrict__ abits,
               const uint32_t* __restrict__ wbits,
               const int*      __restrict__ corr,
               const float*    __restrict__ alpha,
               const float*    __restrict__ Ksc,
               const float*    __restrict__ res,
               float*          __restrict__ out,
               float*          __restrict__ p1,
               float*          __restrict__ p2)
{
    __shared__ __align__(16) uint32_t ws[64 * 72];      // 18 KB weights
    __shared__ __align__(16) uint32_t sact[4 * PW * 8]; // 7.25 KB activations
    __shared__ int   scorr[64 * 9];                     // 2.25 KB
    __shared__ float sal[64];

    const int tid    = threadIdx.x;
    const int ocbase = blockIdx.y * 64;
    const int pix0   = blockIdx.x * 64;
    const int n      = pix0 / HWH;               // 64 | 3136 -> one image/block
    const int pimg0  = pix0 - n * HWH;
    const int r0     = pimg0 / WWD;              // first unpadded row in block

    // ---- cooperative loads ----
    for (int i = tid; i < 64 * 72; i += 256) ws[i] = wbits[ocbase * 72 + i];
    {   // activation tile: padded rows r0..r0+3 of image n, fully contiguous
        const uint4* src = (const uint4*)(abits + ((size_t)n * PIMG + r0 * PW) * 8);
        uint4* dst = (uint4*)sact;
        #pragma unroll
        for (int it = 0; it < 2; it++) {
            const int i = tid + it * 256;
            if (i < 4 * PW * 2) dst[i] = src[i];
        }
    }
    for (int i = tid; i < 64 * 9; i += 256)  scorr[i] = corr[ocbase * 9 + i];
    if (tid < 64) sal[tid] = alpha[ocbase + tid];
    __syncthreads();

    const int lane = tid & 31;
    const int wy   = tid >> 5;
    const int pa = pimg0 + lane;
    const int pb = pa + 32;
    const int hA = pa / WWD, wA = pa - hA * WWD;
    const int hB = pb / WWD, wB = pb - hB * WWD;
    const float kvA = Ksc[pix0 + lane];
    const float kvB = Ksc[pix0 + 32 + lane];

    // smem tile coords: pixel (h,w) -> tile row h+1-r0, col w+1
    const uint32_t* tA = sact + ((hA + 1 - r0) * PW + (wA + 1)) * 8;
    const uint32_t* tB = sact + ((hB + 1 - r0) * PW + (wB + 1)) * 8;

    int accA[8], accB[8];
    #pragma unroll
    for (int i = 0; i < 8; i++) { accA[i] = 0; accB[i] = 0; }

    const uint32_t* wsp = ws + (wy * 8) * 72;

    #pragma unroll
    for (int t = 0; t < 9; t++) {
        const int off = ((t / 3 - 1) * PW + (t % 3 - 1)) * 8;   // compile-time
        const uint4 a0A = *(const uint4*)(tA + off);
        const uint4 a1A = *(const uint4*)(tA + off + 4);
        const uint4 a0B = *(const uint4*)(tB + off);
        const uint4 a1B = *(const uint4*)(tB + off + 4);
        const uint32_t* wt = wsp + t * 8;
        #pragma unroll
        for (int i = 0; i < 8; i++) {
            const uint4 w0 = *(const uint4*)(wt + i * 72);
            const uint4 w1 = *(const uint4*)(wt + i * 72 + 4);
            accA[i] += ((__popc(a0A.x ^ w0.x) + __popc(a0A.y ^ w0.y))
                      + (__popc(a0A.z ^ w0.z) + __popc(a0A.w ^ w0.w)))
                     + ((__popc(a1A.x ^ w1.x) + __popc(a1A.y ^ w1.y))
                      + (__popc(a1A.z ^ w1.z) + __popc(a1A.w ^ w1.w)));
            accB[i] += ((__popc(a0B.x ^ w0.x) + __popc(a0B.y ^ w0.y))
                      + (__popc(a0B.z ^ w0.z) + __popc(a0B.w ^ w0.w)))
                     + ((__popc(a1B.x ^ w1.x) + __popc(a1B.y ^ w1.y))
                      + (__popc(a1B.z ^ w1.z) + __popc(a1B.w ^ w1.w)));
        }
    }

    // ---- boundary corrections (exact): remove guard-tap popc(w) terms ----
    const unsigned mA = (hA == 0 ? 0x007u : 0u) | (hA == HH - 1 ? 0x1C0u : 0u)
                      | (wA == 0 ? 0x049u : 0u) | (wA == WWD - 1 ? 0x124u : 0u);
    const unsigned mB = (hB == 0 ? 0x007u : 0u) | (hB == HH - 1 ? 0x1C0u : 0u)
                      | (wB == 0 ? 0x049u : 0u) | (wB == WWD - 1 ? 0x124u : 0u);
    int corA[8], corB[8];
    #pragma unroll
    for (int i = 0; i < 8; i++) { corA[i] = 0; corB[i] = 0; }
    if (mA | mB) {
        #pragma unroll
        for (int t = 0; t < 9; t++) {
            const int* cp = scorr + (wy * 8) * 9 + t;
            if ((mA >> t) & 1) {
                #pragma unroll
                for (int i = 0; i < 8; i++) corA[i] += cp[i * 9];
            }
            if ((mB >> t) & 1) {
                #pragma unroll
                for (int i = 0; i < 8; i++) corB[i] += cp[i * 9];
            }
        }
    }

    const size_t obaseA = (size_t)n * CC * HWH + pa;
    const size_t obaseB = (size_t)n * CC * HWH + pb;
    #pragma unroll
    for (int i = 0; i < 8; i++) {
        const int oc = ocbase + wy * 8 + i;
        const float al = sal[wy * 8 + i];
        float vA = al * kvA * (float)(KKT - 2 * accA[i] - corA[i]);
        float vB = al * kvB * (float)(KKT - 2 * accB[i] - corB[i]);
        const size_t iA = obaseA + (size_t)oc * HWH;
        const size_t iB = obaseB + (size_t)oc * HWH;
        if (FUSE_RES) { vA += res[iA]; vB += res[iB]; }
        vA = fmaxf(vA, 0.f);
        vB = fmaxf(vB, 0.f);
        out[iA] = vA;
        out[iB] = vB;
        if (STATS) {
            float sv = vA + vB;
            float sq = vA * vA + vB * vB;
            #pragma unroll
            for (int o = 16; o > 0; o >>= 1) {
                sv += __shfl_xor_sync(0xffffffffu, sv, o);
                sq += __shfl_xor_sync(0xffffffffu, sq, o);
            }
            if (lane == 0) {
                p1[(size_t)oc * GRIDX + blockIdx.x] = sv;
                p2[(size_t)oc * GRIDX + blockIdx.x] = sq;
            }
        }
    }
}

// ================================ launcher =====================================
extern "C" void kernel_launch(void* const* d_in, const int* in_sizes, int n_in,
                              void* d_out, int out_size)
{
    (void)in_sizes; (void)n_in; (void)out_size;
    const float* x  = (const float*)d_in[0];
    const float* g1 = (const float*)d_in[1];
    const float* b1 = (const float*)d_in[2];
    const float* w1 = (const float*)d_in[3];
    const float* g2 = (const float*)d_in[4];
    const float* b2 = (const float*)d_in[5];
    const float* w2 = (const float*)d_in[6];
    float* out = (float*)d_out;

    uint32_t *abits, *wbits;
    int *corr;
    float *alpha, *a, *K, *s1, *h1, *s2, *h2, *r, *p1, *p2;
    cudaGetSymbolAddress((void**)&abits, g_abits);
    cudaGetSymbolAddress((void**)&wbits, g_wbits);
    cudaGetSymbolAddress((void**)&corr,  g_corr);
    cudaGetSymbolAddress((void**)&alpha, g_alpha);
    cudaGetSymbolAddress((void**)&a,     g_a);
    cudaGetSymbolAddress((void**)&K,     g_K);
    cudaGetSymbolAddress((void**)&s1,    g_s1);
    cudaGetSymbolAddress((void**)&h1,    g_h1);
    cudaGetSymbolAddress((void**)&s2,    g_s2);
    cudaGetSymbolAddress((void**)&h2,    g_h2);
    cudaGetSymbolAddress((void**)&r,     g_r);
    cudaGetSymbolAddress((void**)&p1,    g_p1);
    cudaGetSymbolAddress((void**)&p2,    g_p2);

    const dim3 cgrid(GRIDX, 4);

    // ---- stage 1: BN1 -> pack -> K1 -> binary conv1 (+ReLU, +BN2 partials) ----
    bn_stats_kernel<<<CC, 512>>>(x, g1, b1, s1, h1);
    wprep_kernel<<<CC, 256>>>(w1, alpha, wbits, corr);
    bn_apply_pack_kernel<<<NPIX / 32, 256>>>(x, s1, h1, abits, a);
    box3_kernel<<<(NPIX + 255) / 256, 256>>>(a, K);
    binconv_kernel<false, true><<<cgrid, 256>>>(abits, wbits, corr, alpha, K, nullptr, r, p1, p2);

    // ---- stage 2: BN2(finalize) -> pack -> K2 -> conv2 + identity + ReLU ----
    bn2_finalize_kernel<<<CC, 256>>>(p1, p2, g2, b2, s2, h2);
    wprep_kernel<<<CC, 256>>>(w2, alpha, wbits, corr);
    bn_apply_pack_kernel<<<NPIX / 32, 256>>>(r, s2, h2, abits, a);
    box3_kernel<<<(NPIX + 255) / 256, 256>>>(a, K);
    binconv_kernel<true, false><<<cgrid, 256>>>(abits, wbits, corr, alpha, K, x, out, p1, p2);
}

// round 16
// speedup vs baseline: 3.9348x; 1.1313x over previous
#include <cuda_runtime.h>
#include <cstdint>

#define NB    32
#define CC    256
#define HH    56
#define WWD   56
#define HWH   (HH*WWD)        /* 3136  */
#define NPIX  (NB*HWH)        /* 100352 */
#define KKT   2304            /* 256*9 */
#define EPSV  1e-5f
#define GRIDX (NPIX/64)       /* 1568 */
#define PW    58              /* padded width  */
#define PIMG  (PW*PW)         /* 3364 padded px per image */

// ---------------- static device scratch (no allocations allowed) ----------------
// Padded activation bits: zero guard ring per image (globals are zero-init;
// guards never written). Guard taps contribute popc(w), removed exactly in the
// epilogue via per-(oc,tap) corrections.
__device__ uint32_t g_abits[NB * PIMG * 8];   // 3.44 MB
__device__ uint32_t g_wbits[CC * 72];         // packed weight bits, 72 words / oc
__device__ int      g_corr[CC * 9];           // 256 - 2*popc(weights of tap)
__device__ float    g_alpha[CC];
__device__ float    g_a[NPIX];                // channel mean per pixel
__device__ float    g_K[NPIX];                // 3x3 box of g_a / 9
__device__ float    g_s1[CC], g_h1[CC];       // bn1 scale / shift
__device__ float    g_s2[CC], g_h2[CC];       // bn2 scale / shift
__device__ float    g_p1[CC * GRIDX];         // bn2 partial sums   (1.6MB)
__device__ float    g_p2[CC * GRIDX];         // bn2 partial sumsq  (1.6MB)
__device__ float    g_r[(size_t)NPIX * CC];   // relu(conv1) fp32 (102.8 MB)

// ============== BN1 statistics: one block per channel, float4 + n-unroll =======
__global__ void bn_stats_kernel(const float* __restrict__ x,
                                const float* __restrict__ gamma,
                                const float* __restrict__ beta,
                                float* __restrict__ scale,
                                float* __restrict__ shift)
{
    const int c = blockIdx.x;
    float s = 0.f, s2 = 0.f;
    for (int n = 0; n < NB; n += 2) {
        const float4* pa = (const float4*)(x + ((size_t)n * CC + c) * HWH);
        const float4* pb = (const float4*)(x + ((size_t)(n + 1) * CC + c) * HWH);
        for (int i = threadIdx.x; i < HWH / 4; i += blockDim.x) {
            float4 va = pa[i], vb = pb[i];
            s  += (va.x + va.y) + (va.z + va.w) + (vb.x + vb.y) + (vb.z + vb.w);
            s2 += (va.x*va.x + va.y*va.y) + (va.z*va.z + va.w*va.w)
                + (vb.x*vb.x + vb.y*vb.y) + (vb.z*vb.z + vb.w*vb.w);
        }
    }
    __shared__ float sh[512], sh2[512];
    sh[threadIdx.x]  = s;
    sh2[threadIdx.x] = s2;
    __syncthreads();
    for (int o = 256; o > 0; o >>= 1) {
        if (threadIdx.x < o) {
            sh[threadIdx.x]  += sh[threadIdx.x + o];
            sh2[threadIdx.x] += sh2[threadIdx.x + o];
        }
        __syncthreads();
    }
    if (threadIdx.x == 0) {
        const float inv_n = 1.0f / (float)((size_t)NB * HWH);
        float m   = sh[0] * inv_n;
        float var = sh2[0] * inv_n - m * m;
        float sc  = gamma[c] * rsqrtf(var + EPSV);
        scale[c] = sc;
        shift[c] = beta[c] - m * sc;
    }
}

// ======== BN2 finalize from deterministic partials written by conv1 ============
__global__ void bn2_finalize_kernel(const float* __restrict__ p1,
                                    const float* __restrict__ p2,
                                    const float* __restrict__ gamma,
                                    const float* __restrict__ beta,
                                    float* __restrict__ scale,
                                    float* __restrict__ shift)
{
    const int c = blockIdx.x;
    float s = 0.f, s2 = 0.f;
    for (int i = threadIdx.x; i < GRIDX; i += 256) {
        s  += p1[c * GRIDX + i];
        s2 += p2[c * GRIDX + i];
    }
    __shared__ float sh[256], sh2[256];
    sh[threadIdx.x]  = s;
    sh2[threadIdx.x] = s2;
    __syncthreads();
    for (int o = 128; o > 0; o >>= 1) {
        if (threadIdx.x < o) {
            sh[threadIdx.x]  += sh[threadIdx.x + o];
            sh2[threadIdx.x] += sh2[threadIdx.x + o];
        }
        __syncthreads();
    }
    if (threadIdx.x == 0) {
        const float inv_n = 1.0f / (float)((size_t)NB * HWH);
        float m   = sh[0] * inv_n;
        float var = sh2[0] * inv_n - m * m;
        float sc  = gamma[c] * rsqrtf(var + EPSV);
        scale[c] = sc;
        shift[c] = beta[c] - m * sc;
    }
}

// ======= weight prep: alpha[oc] + bit pack + per-tap popcount correction =======
__global__ void wprep_kernel(const float* __restrict__ w,
                             float* __restrict__ alpha,
                             uint32_t* __restrict__ wbits,
                             int* __restrict__ corr)
{
    const int oc = blockIdx.x;
    const float* wp = w + (size_t)oc * KKT;   // [ic][ky][kx]

    float s = 0.f;
    for (int i = threadIdx.x; i < KKT; i += 256) s += fabsf(wp[i]);
    __shared__ float sh[256];
    __shared__ int   spc[72];
    sh[threadIdx.x] = s;
    __syncthreads();
    for (int o = 128; o > 0; o >>= 1) {
        if (threadIdx.x < o) sh[threadIdx.x] += sh[threadIdx.x + o];
        __syncthreads();
    }
    if (threadIdx.x == 0) alpha[oc] = sh[0] * (1.0f / (float)KKT);

    if (threadIdx.x < 72) {
        const int t  = threadIdx.x >> 3;   // tap 0..8 (ky*3+kx)
        const int wd = threadIdx.x & 7;    // word 0..7
        uint32_t bits = 0;
        #pragma unroll
        for (int b = 0; b < 32; b++) {
            int ch = wd * 32 + b;
            float v = wp[ch * 9 + t];
            bits |= (v > 0.f ? 1u : 0u) << b;
        }
        wbits[oc * 72 + t * 8 + wd] = bits;
        spc[threadIdx.x] = __popc(bits);
    }
    __syncthreads();
    if (threadIdx.x < 9) {
        int pc = 0;
        #pragma unroll
        for (int wd = 0; wd < 8; wd++) pc += spc[threadIdx.x * 8 + wd];
        corr[oc * 9 + threadIdx.x] = 256 - 2 * pc;   // guard-tap contribution
    }
}

// ====== BN apply + sign-pack (padded layout) + channel mean ====================
__global__ void bn_apply_pack_kernel(const float* __restrict__ x,
                                     const float* __restrict__ scale,
                                     const float* __restrict__ shift,
                                     uint32_t* __restrict__ abits,
                                     float* __restrict__ amean)
{
    const int lane = threadIdx.x & 31;
    const int wy   = threadIdx.x >> 5;        // channels [32wy, 32wy+32)
    const int pix  = blockIdx.x * 32 + lane;
    const int n = pix / HWH;
    const int p = pix - n * HWH;
    const int h = p / WWD;
    const int w = p - h * WWD;

    const float* base = x + ((size_t)n * CC + wy * 32) * HWH + p;
    uint32_t bits = 0;
    float s = 0.f;
    #pragma unroll
    for (int i = 0; i < 32; i++) {
        const int c = wy * 32 + i;
        float v = fmaf(base[(size_t)i * HWH], scale[c], shift[c]);
        s += v;
        bits |= (v > 0.f ? 1u : 0u) << i;
    }
    abits[((size_t)n * PIMG + (h + 1) * PW + (w + 1)) * 8 + wy] = bits;

    __shared__ float sh[8][32];
    sh[wy][lane] = s;
    __syncthreads();
    if (wy == 0) {
        float t = 0.f;
        #pragma unroll
        for (int k = 0; k < 8; k++) t += sh[k][lane];   // fixed order
        amean[pix] = t * (1.0f / 256.0f);
    }
}

// ================= 3x3 box filter / 9 with zero padding ========================
__global__ void box3_kernel(const float* __restrict__ a, float* __restrict__ K)
{
    const int idx = blockIdx.x * 256 + threadIdx.x;
    if (idx >= NPIX) return;
    const int n = idx / HWH;
    const int p = idx - n * HWH;
    const int h = p / WWD;
    const int w = p - h * WWD;
    const float* an = a + (size_t)n * HWH;
    float s = 0.f;
    #pragma unroll
    for (int dy = -1; dy <= 1; dy++) {
        int hh = h + dy;
        if (hh < 0 || hh >= HH) continue;
        #pragma unroll
        for (int dx = -1; dx <= 1; dx++) {
            int ww = w + dx;
            if (ww < 0 || ww >= WWD) continue;
            s += an[hh * WWD + ww];
        }
    }
    K[idx] = s * (1.0f / 9.0f);
}

// -------- 3:2 carry-save adder: sum-of-popcounts preserved as s + 2c ----------
__device__ __forceinline__ void csa(uint32_t a, uint32_t b, uint32_t c,
                                    uint32_t& s, uint32_t& cy)
{
    s  = a ^ b ^ c;                      // one LOP3
    cy = (a & b) | (c & (a | b));        // one LOP3 (majority)
}

// ================= binary conv: XNOR + CSA-compressed popcount =================
// grid (NPIX/64, 4), block 256 = 8 warps; warp wy -> oc [ocb+8wy,+8), lane ->
// pixels (pix0+lane, pix0+32+lane). Per (oc,px,tap): 8 XOR words are CSA-
// compressed 8->4 before POPC (s2:x1, x7:x1, sc:x2, cc:x4), halving POPC count
// (POPC is the quarter-rate binding pipe). Integer-exact.
template <bool FUSE_RES, bool STATS>
__global__ void __launch_bounds__(256)
binconv_kernel(const uint32_t* __restrict__ abits,
               const uint32_t* __restrict__ wbits,
               const int*      __restrict__ corr,
               const float*    __restrict__ alpha,
               const float*    __restrict__ Ksc,
               const float*    __restrict__ res,
               float*          __restrict__ out,
               float*          __restrict__ p1,
               float*          __restrict__ p2)
{
    __shared__ __align__(16) uint32_t ws[64 * 72];      // 18 KB weights
    __shared__ __align__(16) uint32_t sact[4 * PW * 8]; // 7.25 KB activations
    __shared__ int   scorr[64 * 9];                     // 2.25 KB
    __shared__ float sal[64];

    const int tid    = threadIdx.x;
    const int ocbase = blockIdx.y * 64;
    const int pix0   = blockIdx.x * 64;
    const int n      = pix0 / HWH;               // 64 | 3136 -> one image/block
    const int pimg0  = pix0 - n * HWH;
    const int r0     = pimg0 / WWD;              // first unpadded row in block

    // ---- cooperative loads ----
    for (int i = tid; i < 64 * 72; i += 256) ws[i] = wbits[ocbase * 72 + i];
    {   // activation tile: padded rows r0..r0+3 of image n, fully contiguous
        const uint4* src = (const uint4*)(abits + ((size_t)n * PIMG + r0 * PW) * 8);
        uint4* dst = (uint4*)sact;
        #pragma unroll
        for (int it = 0; it < 2; it++) {
            const int i = tid + it * 256;
            if (i < 4 * PW * 2) dst[i] = src[i];
        }
    }
    for (int i = tid; i < 64 * 9; i += 256)  scorr[i] = corr[ocbase * 9 + i];
    if (tid < 64) sal[tid] = alpha[ocbase + tid];
    __syncthreads();

    const int lane = tid & 31;
    const int wy   = tid >> 5;
    const int pa = pimg0 + lane;
    const int pb = pa + 32;
    const int hA = pa / WWD, wA = pa - hA * WWD;
    const int hB = pb / WWD, wB = pb - hB * WWD;
    const float kvA = Ksc[pix0 + lane];
    const float kvB = Ksc[pix0 + 32 + lane];

    // smem tile coords: pixel (h,w) -> tile row h+1-r0, col w+1
    const uint32_t* tA = sact + ((hA + 1 - r0) * PW + (wA + 1)) * 8;
    const uint32_t* tB = sact + ((hB + 1 - r0) * PW + (wB + 1)) * 8;

    int accA[8], accB[8];
    #pragma unroll
    for (int i = 0; i < 8; i++) { accA[i] = 0; accB[i] = 0; }

    const uint32_t* wsp = ws + (wy * 8) * 72;

    #pragma unroll
    for (int t = 0; t < 9; t++) {
        const int off = ((t / 3 - 1) * PW + (t % 3 - 1)) * 8;   // compile-time
        const uint4 a0A = *(const uint4*)(tA + off);
        const uint4 a1A = *(const uint4*)(tA + off + 4);
        const uint4 a0B = *(const uint4*)(tB + off);
        const uint4 a1B = *(const uint4*)(tB + off + 4);
        const uint32_t* wt = wsp + t * 8;
        #pragma unroll
        for (int i = 0; i < 8; i++) {
            const uint4 w0 = *(const uint4*)(wt + i * 72);
            const uint4 w1 = *(const uint4*)(wt + i * 72 + 4);
            // ---- pixel A: 8 XOR -> CSA 8->4 -> 4 POPC ----
            {
                uint32_t x0 = a0A.x ^ w0.x, x1 = a0A.y ^ w0.y;
                uint32_t x2 = a0A.z ^ w0.z, x3 = a0A.w ^ w0.w;
                uint32_t x4 = a1A.x ^ w1.x, x5 = a1A.y ^ w1.y;
                uint32_t x6 = a1A.z ^ w1.z, x7 = a1A.w ^ w1.w;
                uint32_t s0, c0, s1, c1, s2, c2, sc, cc;
                csa(x0, x1, x2, s0, c0);
                csa(x3, x4, x5, s1, c1);
                csa(s0, s1, x6, s2, c2);
                csa(c0, c1, c2, sc, cc);
                accA[i] += (__popc(s2) + __popc(x7))
                         + 2 * __popc(sc) + 4 * __popc(cc);
            }
            // ---- pixel B ----
            {
                uint32_t x0 = a0B.x ^ w0.x, x1 = a0B.y ^ w0.y;
                uint32_t x2 = a0B.z ^ w0.z, x3 = a0B.w ^ w0.w;
                uint32_t x4 = a1B.x ^ w1.x, x5 = a1B.y ^ w1.y;
                uint32_t x6 = a1B.z ^ w1.z, x7 = a1B.w ^ w1.w;
                uint32_t s0, c0, s1, c1, s2, c2, sc, cc;
                csa(x0, x1, x2, s0, c0);
                csa(x3, x4, x5, s1, c1);
                csa(s0, s1, x6, s2, c2);
                csa(c0, c1, c2, sc, cc);
                accB[i] += (__popc(s2) + __popc(x7))
                         + 2 * __popc(sc) + 4 * __popc(cc);
            }
        }
    }

    // ---- boundary corrections (exact): remove guard-tap popc(w) terms ----
    const unsigned mA = (hA == 0 ? 0x007u : 0u) | (hA == HH - 1 ? 0x1C0u : 0u)
                      | (wA == 0 ? 0x049u : 0u) | (wA == WWD - 1 ? 0x124u : 0u);
    const unsigned mB = (hB == 0 ? 0x007u : 0u) | (hB == HH - 1 ? 0x1C0u : 0u)
                      | (wB == 0 ? 0x049u : 0u) | (wB == WWD - 1 ? 0x124u : 0u);
    int corA[8], corB[8];
    #pragma unroll
    for (int i = 0; i < 8; i++) { corA[i] = 0; corB[i] = 0; }
    if (mA | mB) {
        #pragma unroll
        for (int t = 0; t < 9; t++) {
            const int* cp = scorr + (wy * 8) * 9 + t;
            if ((mA >> t) & 1) {
                #pragma unroll
                for (int i = 0; i < 8; i++) corA[i] += cp[i * 9];
            }
            if ((mB >> t) & 1) {
                #pragma unroll
                for (int i = 0; i < 8; i++) corB[i] += cp[i * 9];
            }
        }
    }

    const size_t obaseA = (size_t)n * CC * HWH + pa;
    const size_t obaseB = (size_t)n * CC * HWH + pb;
    #pragma unroll
    for (int i = 0; i < 8; i++) {
        const int oc = ocbase + wy * 8 + i;
        const float al = sal[wy * 8 + i];
        float vA = al * kvA * (float)(KKT - 2 * accA[i] - corA[i]);
        float vB = al * kvB * (float)(KKT - 2 * accB[i] - corB[i]);
        const size_t iA = obaseA + (size_t)oc * HWH;
        const size_t iB = obaseB + (size_t)oc * HWH;
        if (FUSE_RES) { vA += res[iA]; vB += res[iB]; }
        vA = fmaxf(vA, 0.f);
        vB = fmaxf(vB, 0.f);
        out[iA] = vA;
        out[iB] = vB;
        if (STATS) {
            float sv = vA + vB;
            float sq = vA * vA + vB * vB;
            #pragma unroll
            for (int o = 16; o > 0; o >>= 1) {
                sv += __shfl_xor_sync(0xffffffffu, sv, o);
                sq += __shfl_xor_sync(0xffffffffu, sq, o);
            }
            if (lane == 0) {
                p1[(size_t)oc * GRIDX + blockIdx.x] = sv;
                p2[(size_t)oc * GRIDX + blockIdx.x] = sq;
            }
        }
    }
}

// ================================ launcher =====================================
extern "C" void kernel_launch(void* const* d_in, const int* in_sizes, int n_in,
                              void* d_out, int out_size)
{
    (void)in_sizes; (void)n_in; (void)out_size;
    const float* x  = (const float*)d_in[0];
    const float* g1 = (const float*)d_in[1];
    const float* b1 = (const float*)d_in[2];
    const float* w1 = (const float*)d_in[3];
    const float* g2 = (const float*)d_in[4];
    const float* b2 = (const float*)d_in[5];
    const float* w2 = (const float*)d_in[6];
    float* out = (float*)d_out;

    uint32_t *abits, *wbits;
    int *corr;
    float *alpha, *a, *K, *s1, *h1, *s2, *h2, *r, *p1, *p2;
    cudaGetSymbolAddress((void**)&abits, g_abits);
    cudaGetSymbolAddress((void**)&wbits, g_wbits);
    cudaGetSymbolAddress((void**)&corr,  g_corr);
    cudaGetSymbolAddress((void**)&alpha, g_alpha);
    cudaGetSymbolAddress((void**)&a,     g_a);
    cudaGetSymbolAddress((void**)&K,     g_K);
    cudaGetSymbolAddress((void**)&s1,    g_s1);
    cudaGetSymbolAddress((void**)&h1,    g_h1);
    cudaGetSymbolAddress((void**)&s2,    g_s2);
    cudaGetSymbolAddress((void**)&h2,    g_h2);
    cudaGetSymbolAddress((void**)&r,     g_r);
    cudaGetSymbolAddress((void**)&p1,    g_p1);
    cudaGetSymbolAddress((void**)&p2,    g_p2);

    const dim3 cgrid(GRIDX, 4);

    // ---- stage 1: BN1 -> pack -> K1 -> binary conv1 (+ReLU, +BN2 partials) ----
    bn_stats_kernel<<<CC, 512>>>(x, g1, b1, s1, h1);
    wprep_kernel<<<CC, 256>>>(w1, alpha, wbits, corr);
    bn_apply_pack_kernel<<<NPIX / 32, 256>>>(x, s1, h1, abits, a);
    box3_kernel<<<(NPIX + 255) / 256, 256>>>(a, K);
    binconv_kernel<false, true><<<cgrid, 256>>>(abits, wbits, corr, alpha, K, nullptr, r, p1, p2);

    // ---- stage 2: BN2(finalize) -> pack -> K2 -> conv2 + identity + ReLU ----
    bn2_finalize_kernel<<<CC, 256>>>(p1, p2, g2, b2, s2, h2);
    wprep_kernel<<<CC, 256>>>(w2, alpha, wbits, corr);
    bn_apply_pack_kernel<<<NPIX / 32, 256>>>(r, s2, h2, abits, a);
    box3_kernel<<<(NPIX + 255) / 256, 256>>>(a, K);
    binconv_kernel<true, false><<<cgrid, 256>>>(abits, wbits, corr, alpha, K, x, out, p1, p2);
}